// round 4
// baseline (speedup 1.0000x reference)
#include <cuda_runtime.h>
#include <cuda_bf16.h>

// GCNConv: out = D^-1/2 (A + I) D^-1/2 (x @ W) + b
// Inputs (metadata order): x[f32 N*128], edge_index[2*E int64 OR int32 -- auto-detected],
//                          W[f32 128*128], b[f32 128]
// Output: f32 N*128

#define MAX_N 100000
#define MAX_E 1600000
#define C 128

// Scratch (allocation-free rule: __device__ globals)
__device__ int   g_is64;
__device__ int   g_src[MAX_E];
__device__ int   g_dst[MAX_E];
__device__ int   g_deg[MAX_N];
__device__ float g_dinv[MAX_N];
__device__ float g_h[(size_t)MAX_N * C];   // 51.2 MB, fits in L2

// ---------------------------------------------------------------------------
// Dtype detection: int64 payload with values < 2^31 has zero high words at all
// odd int32 positions; int32 payload has live indices there.
// ---------------------------------------------------------------------------
__global__ void detect_dtype(const int* __restrict__ ei32) {
    __shared__ int any_nonzero;
    if (threadIdx.x == 0) any_nonzero = 0;
    __syncthreads();
    for (int i = threadIdx.x; i < 512; i += blockDim.x)
        if (ei32[2 * i + 1] != 0) any_nonzero = 1;
    __syncthreads();
    if (threadIdx.x == 0) g_is64 = (any_nonzero == 0);
}

__global__ void convert_edges(const void* __restrict__ ei, int E) {
    int e = blockIdx.x * blockDim.x + threadIdx.x;
    if (e >= E) return;
    if (g_is64) {
        const long long* p = (const long long*)ei;
        g_src[e] = (int)p[e];
        g_dst[e] = (int)p[(size_t)E + e];
    } else {
        const int* p = (const int*)ei;
        g_src[e] = p[e];
        g_dst[e] = p[(size_t)E + e];
    }
}

// ---------------------------------------------------------------------------
// Degree / normalization
// ---------------------------------------------------------------------------
__global__ void init_deg(int n) {
    int i = blockIdx.x * blockDim.x + threadIdx.x;
    if (i < n) g_deg[i] = 1;   // self loop
}

__global__ void count_deg(int E) {
    int e = blockIdx.x * blockDim.x + threadIdx.x;
    if (e < E) atomicAdd(&g_deg[g_dst[e]], 1);
}

__global__ void compute_dinv(int n) {
    int i = blockIdx.x * blockDim.x + threadIdx.x;
    if (i < n) g_dinv[i] = rsqrtf((float)g_deg[i]);  // deg >= 1 always
}

// ---------------------------------------------------------------------------
// GEMM: h[N,128] = x[N,128] @ W[128,128]
// BM=64 rows per block, 256 threads, thread tile 4 rows x 8 cols (split 4+4).
// ---------------------------------------------------------------------------
#define BM 64
#define BK 16

__global__ __launch_bounds__(256) void gemm_xw(const float* __restrict__ x,
                                               const float* __restrict__ W,
                                               int n) {
    __shared__ float xs[BK][BM + 4];   // transposed x tile (pad vs conflicts)
    __shared__ float ws[BK][C];

    const int tid = threadIdx.x;
    const int tx  = tid & 15;          // 0..15 -> column group
    const int ty  = tid >> 4;          // 0..15 -> row group (4 rows each)
    const int row0 = blockIdx.x * BM;

    float acc[4][8];
#pragma unroll
    for (int i = 0; i < 4; i++)
#pragma unroll
        for (int j = 0; j < 8; j++) acc[i][j] = 0.f;

    for (int k0 = 0; k0 < C; k0 += BK) {
        // load x tile [BM x BK] -> xs[k][row]; thread: row = tid/4, kq = tid%4
        {
            int r  = tid >> 2;
            int kq = tid & 3;
            int grow = row0 + r;
            float4 v = make_float4(0.f, 0.f, 0.f, 0.f);
            if (grow < n)
                v = *(const float4*)(x + (size_t)grow * C + k0 + kq * 4);
            xs[kq * 4 + 0][r] = v.x;
            xs[kq * 4 + 1][r] = v.y;
            xs[kq * 4 + 2][r] = v.z;
            xs[kq * 4 + 3][r] = v.w;
        }
        // load W tile [BK x 128]; thread: kk = tid/32, cq = tid%32, 2 rows
        {
            int kk = tid >> 5;
            int cq = tid & 31;
            *(float4*)&ws[kk][cq * 4] =
                *(const float4*)(W + (size_t)(k0 + kk) * C + cq * 4);
            *(float4*)&ws[kk + 8][cq * 4] =
                *(const float4*)(W + (size_t)(k0 + kk + 8) * C + cq * 4);
        }
        __syncthreads();

#pragma unroll
        for (int k = 0; k < BK; k++) {
            float4 xv = *(const float4*)&xs[k][ty * 4];
            float4 wa = *(const float4*)&ws[k][tx * 4];        // cols tx*4..+3
            float4 wb = *(const float4*)&ws[k][64 + tx * 4];   // cols 64+tx*4..+3
            float xr[4] = {xv.x, xv.y, xv.z, xv.w};
            float wr[8] = {wa.x, wa.y, wa.z, wa.w, wb.x, wb.y, wb.z, wb.w};
#pragma unroll
            for (int i = 0; i < 4; i++)
#pragma unroll
                for (int j = 0; j < 8; j++)
                    acc[i][j] = fmaf(xr[i], wr[j], acc[i][j]);
        }
        __syncthreads();
    }

#pragma unroll
    for (int i = 0; i < 4; i++) {
        int row = row0 + ty * 4 + i;
        if (row < n) {
            float* hp = g_h + (size_t)row * C;
            *(float4*)(hp + tx * 4)      = make_float4(acc[i][0], acc[i][1], acc[i][2], acc[i][3]);
            *(float4*)(hp + 64 + tx * 4) = make_float4(acc[i][4], acc[i][5], acc[i][6], acc[i][7]);
        }
    }
}

// ---------------------------------------------------------------------------
// out[i] = h[i] * dinv[i]^2 + b   (self loop + bias; also initializes out)
// ---------------------------------------------------------------------------
__global__ void selfloop_bias(const float* __restrict__ b, float* __restrict__ out, int n) {
    int idx = blockIdx.x * blockDim.x + threadIdx.x;   // over n*32
    if (idx >= n * 32) return;
    int node = idx >> 5;
    int q    = idx & 31;
    float s  = g_dinv[node];
    s = s * s;
    float4 hv = *(const float4*)(g_h + (size_t)node * C + q * 4);
    float4 bv = *(const float4*)(b + q * 4);
    float4 o;
    o.x = fmaf(hv.x, s, bv.x);
    o.y = fmaf(hv.y, s, bv.y);
    o.z = fmaf(hv.z, s, bv.z);
    o.w = fmaf(hv.w, s, bv.w);
    *(float4*)(out + (size_t)node * C + q * 4) = o;
}

// ---------------------------------------------------------------------------
// Edge scatter: one warp per edge. Gather contiguous 512B h[src] row,
// scale by dinv[src]*dinv[dst], vector-reduce into out[dst].
// ---------------------------------------------------------------------------
__global__ __launch_bounds__(256) void edge_scatter(float* __restrict__ out, int E) {
    int gw   = (blockIdx.x * blockDim.x + threadIdx.x) >> 5;
    int lane = threadIdx.x & 31;
    if (gw >= E) return;
    int src = g_src[gw];
    int dst = g_dst[gw];
    float norm = g_dinv[src] * g_dinv[dst];

    float4 v = *(const float4*)(g_h + (size_t)src * C + lane * 4);
    v.x *= norm; v.y *= norm; v.z *= norm; v.w *= norm;

    float* p = out + (size_t)dst * C + lane * 4;
    asm volatile("red.global.add.v4.f32 [%0], {%1, %2, %3, %4};"
                 :: "l"(p), "f"(v.x), "f"(v.y), "f"(v.z), "f"(v.w)
                 : "memory");
}

// ---------------------------------------------------------------------------
extern "C" void kernel_launch(void* const* d_in, const int* in_sizes, int n_in,
                              void* d_out, int out_size) {
    const float* x  = (const float*)d_in[0];
    const void*  ei = d_in[1];
    const float* W  = (const float*)d_in[2];
    const float* b  = (const float*)d_in[3];
    float* out = (float*)d_out;

    int n = in_sizes[0] / C;
    int E = in_sizes[1] / 2;

    detect_dtype<<<1, 256>>>((const int*)ei);
    convert_edges<<<(E + 255) / 256, 256>>>(ei, E);
    init_deg<<<(n + 255) / 256, 256>>>(n);
    count_deg<<<(E + 255) / 256, 256>>>(E);
    compute_dinv<<<(n + 255) / 256, 256>>>(n);
    gemm_xw<<<(n + BM - 1) / BM, 256>>>(x, W, n);
    selfloop_bias<<<(n * 32 + 255) / 256, 256>>>(b, out, n);
    edge_scatter<<<(E + 7) / 8, 256>>>(out, E);
}

// round 5
// speedup vs baseline: 1.5215x; 1.5215x over previous
#include <cuda_runtime.h>
#include <cuda_bf16.h>

// GCNConv: out = D^-1/2 (A + I) D^-1/2 (x @ W) + b
// Inputs: x[f32 N*128], edge_index[2*E int64 OR int32 -- auto-detected],
//         W[f32 128*128], b[f32 128].  Output: f32 N*128
//
// R5: CSR-by-dst + register-accumulating gather (no float atomics).

#define MAX_N 100000
#define MAX_E 1600000
#define C 128
#define SCAN_B 512

__device__ int   g_is64;
__device__ int   g_deg[MAX_N];
__device__ float g_dinv[MAX_N];
__device__ int   g_rowptr[MAX_N + 1];
__device__ int   g_cursor[MAX_N];
__device__ int   g_bsum[(MAX_N + SCAN_B - 1) / SCAN_B + 1];
__device__ int   g_csrc[MAX_E];
__device__ float g_h[(size_t)MAX_N * C];   // 51.2 MB, L2-resident

// ---------------------------------------------------------------------------
// Edge index dtype detection (int64 payload w/ values < 2^31 has zero high
// words at all odd int32 positions; int32 payload has live indices there).
// ---------------------------------------------------------------------------
__global__ void detect_dtype(const int* __restrict__ ei32) {
    __shared__ int any_nonzero;
    if (threadIdx.x == 0) any_nonzero = 0;
    __syncthreads();
    for (int i = threadIdx.x; i < 512; i += blockDim.x)
        if (ei32[2 * i + 1] != 0) any_nonzero = 1;
    __syncthreads();
    if (threadIdx.x == 0) g_is64 = (any_nonzero == 0);
}

__device__ __forceinline__ int edge_at(const void* ei, size_t idx, int is64) {
    return is64 ? (int)((const long long*)ei)[idx] : ((const int*)ei)[idx];
}

// ---------------------------------------------------------------------------
// Degree / normalization
// ---------------------------------------------------------------------------
__global__ void init_deg(int n) {
    int i = blockIdx.x * blockDim.x + threadIdx.x;
    if (i < n) g_deg[i] = 1;   // self loop
}

__global__ void count_deg(const void* __restrict__ ei, int E) {
    int e = blockIdx.x * blockDim.x + threadIdx.x;
    if (e < E) {
        int dst = edge_at(ei, (size_t)E + e, g_is64);
        atomicAdd(&g_deg[dst], 1);
    }
}

__global__ void compute_dinv(int n) {
    int i = blockIdx.x * blockDim.x + threadIdx.x;
    if (i < n) g_dinv[i] = rsqrtf((float)g_deg[i]);  // deg >= 1 always
}

// ---------------------------------------------------------------------------
// Exclusive scan of (deg-1) -> rowptr  (3-phase)
// ---------------------------------------------------------------------------
__global__ __launch_bounds__(SCAN_B) void scan_phase1(int n) {
    __shared__ int sh[SCAN_B];
    int i = blockIdx.x * SCAN_B + threadIdx.x;
    int v = (i < n) ? (g_deg[i] - 1) : 0;
    sh[threadIdx.x] = v;
    __syncthreads();
    // Hillis-Steele inclusive scan
    for (int off = 1; off < SCAN_B; off <<= 1) {
        int t = (threadIdx.x >= off) ? sh[threadIdx.x - off] : 0;
        __syncthreads();
        sh[threadIdx.x] += t;
        __syncthreads();
    }
    if (i < n) g_rowptr[i] = sh[threadIdx.x] - v;   // exclusive
    if (threadIdx.x == SCAN_B - 1) g_bsum[blockIdx.x] = sh[SCAN_B - 1];
}

__global__ __launch_bounds__(SCAN_B) void scan_phase2(int nb) {
    __shared__ int sh[SCAN_B];
    int v = (threadIdx.x < nb) ? g_bsum[threadIdx.x] : 0;
    sh[threadIdx.x] = v;
    __syncthreads();
    for (int off = 1; off < SCAN_B; off <<= 1) {
        int t = (threadIdx.x >= off) ? sh[threadIdx.x - off] : 0;
        __syncthreads();
        sh[threadIdx.x] += t;
        __syncthreads();
    }
    if (threadIdx.x < nb) g_bsum[threadIdx.x] = sh[threadIdx.x] - v;  // exclusive
}

__global__ void scan_phase3(int n, int E) {
    int i = blockIdx.x * blockDim.x + threadIdx.x;
    if (i < n) {
        int r = g_rowptr[i] + g_bsum[i / SCAN_B];
        g_rowptr[i] = r;
        g_cursor[i] = r;
    }
    if (i == 0) g_rowptr[n] = E;
}

// ---------------------------------------------------------------------------
// Fill CSR: csrc[pos] = src for each edge grouped by dst
// ---------------------------------------------------------------------------
__global__ void fill_csr(const void* __restrict__ ei, int E) {
    int e = blockIdx.x * blockDim.x + threadIdx.x;
    if (e >= E) return;
    int is64 = g_is64;
    int src = edge_at(ei, e, is64);
    int dst = edge_at(ei, (size_t)E + e, is64);
    int p = atomicAdd(&g_cursor[dst], 1);
    g_csrc[p] = src;
}

// ---------------------------------------------------------------------------
// GEMM: h[N,128] = x[N,128] @ W[128,128]
// ---------------------------------------------------------------------------
#define BM 64
#define BK 16

__global__ __launch_bounds__(256) void gemm_xw(const float* __restrict__ x,
                                               const float* __restrict__ W,
                                               int n) {
    __shared__ float xs[BK][BM + 4];
    __shared__ float ws[BK][C];

    const int tid = threadIdx.x;
    const int tx  = tid & 15;
    const int ty  = tid >> 4;
    const int row0 = blockIdx.x * BM;

    float acc[4][8];
#pragma unroll
    for (int i = 0; i < 4; i++)
#pragma unroll
        for (int j = 0; j < 8; j++) acc[i][j] = 0.f;

    for (int k0 = 0; k0 < C; k0 += BK) {
        {
            int r  = tid >> 2;
            int kq = tid & 3;
            int grow = row0 + r;
            float4 v = make_float4(0.f, 0.f, 0.f, 0.f);
            if (grow < n)
                v = *(const float4*)(x + (size_t)grow * C + k0 + kq * 4);
            xs[kq * 4 + 0][r] = v.x;
            xs[kq * 4 + 1][r] = v.y;
            xs[kq * 4 + 2][r] = v.z;
            xs[kq * 4 + 3][r] = v.w;
        }
        {
            int kk = tid >> 5;
            int cq = tid & 31;
            *(float4*)&ws[kk][cq * 4] =
                *(const float4*)(W + (size_t)(k0 + kk) * C + cq * 4);
            *(float4*)&ws[kk + 8][cq * 4] =
                *(const float4*)(W + (size_t)(k0 + kk + 8) * C + cq * 4);
        }
        __syncthreads();

#pragma unroll
        for (int k = 0; k < BK; k++) {
            float4 xv = *(const float4*)&xs[k][ty * 4];
            float4 wa = *(const float4*)&ws[k][tx * 4];
            float4 wb = *(const float4*)&ws[k][64 + tx * 4];
            float xr[4] = {xv.x, xv.y, xv.z, xv.w};
            float wr[8] = {wa.x, wa.y, wa.z, wa.w, wb.x, wb.y, wb.z, wb.w};
#pragma unroll
            for (int i = 0; i < 4; i++)
#pragma unroll
                for (int j = 0; j < 8; j++)
                    acc[i][j] = fmaf(xr[i], wr[j], acc[i][j]);
        }
        __syncthreads();
    }

#pragma unroll
    for (int i = 0; i < 4; i++) {
        int row = row0 + ty * 4 + i;
        if (row < n) {
            float* hp = g_h + (size_t)row * C;
            *(float4*)(hp + tx * 4)      = make_float4(acc[i][0], acc[i][1], acc[i][2], acc[i][3]);
            *(float4*)(hp + 64 + tx * 4) = make_float4(acc[i][4], acc[i][5], acc[i][6], acc[i][7]);
        }
    }
}

// ---------------------------------------------------------------------------
// Aggregate: one warp per dst node. Register accumulation, fused self-loop
// + bias, single vector store. No float atomics. MLP=4 on h-row gathers.
// ---------------------------------------------------------------------------
__global__ __launch_bounds__(256) void aggregate(const float* __restrict__ b,
                                                 float* __restrict__ out, int n) {
    int w    = (blockIdx.x * blockDim.x + threadIdx.x) >> 5;
    int lane = threadIdx.x & 31;
    if (w >= n) return;

    float di = g_dinv[w];
    int j  = g_rowptr[w];
    int j1 = g_rowptr[w + 1];

    // self loop: h[w] * di^2
    float4 hv = *(const float4*)(g_h + (size_t)w * C + lane * 4);
    float s = di * di;
    float4 a0 = make_float4(hv.x * s, hv.y * s, hv.z * s, hv.w * s);
    float4 a1 = make_float4(0.f, 0.f, 0.f, 0.f);
    float4 a2 = make_float4(0.f, 0.f, 0.f, 0.f);
    float4 a3 = make_float4(0.f, 0.f, 0.f, 0.f);

    for (; j + 3 < j1; j += 4) {
        int sA = g_csrc[j], sB = g_csrc[j + 1], sC = g_csrc[j + 2], sD = g_csrc[j + 3];
        float nA = di * g_dinv[sA];
        float nB = di * g_dinv[sB];
        float nC = di * g_dinv[sC];
        float nD = di * g_dinv[sD];
        float4 vA = *(const float4*)(g_h + (size_t)sA * C + lane * 4);
        float4 vB = *(const float4*)(g_h + (size_t)sB * C + lane * 4);
        float4 vC = *(const float4*)(g_h + (size_t)sC * C + lane * 4);
        float4 vD = *(const float4*)(g_h + (size_t)sD * C + lane * 4);
        a0.x = fmaf(vA.x, nA, a0.x); a0.y = fmaf(vA.y, nA, a0.y);
        a0.z = fmaf(vA.z, nA, a0.z); a0.w = fmaf(vA.w, nA, a0.w);
        a1.x = fmaf(vB.x, nB, a1.x); a1.y = fmaf(vB.y, nB, a1.y);
        a1.z = fmaf(vB.z, nB, a1.z); a1.w = fmaf(vB.w, nB, a1.w);
        a2.x = fmaf(vC.x, nC, a2.x); a2.y = fmaf(vC.y, nC, a2.y);
        a2.z = fmaf(vC.z, nC, a2.z); a2.w = fmaf(vC.w, nC, a2.w);
        a3.x = fmaf(vD.x, nD, a3.x); a3.y = fmaf(vD.y, nD, a3.y);
        a3.z = fmaf(vD.z, nD, a3.z); a3.w = fmaf(vD.w, nD, a3.w);
    }
    for (; j < j1; j++) {
        int sA = g_csrc[j];
        float nA = di * g_dinv[sA];
        float4 vA = *(const float4*)(g_h + (size_t)sA * C + lane * 4);
        a0.x = fmaf(vA.x, nA, a0.x); a0.y = fmaf(vA.y, nA, a0.y);
        a0.z = fmaf(vA.z, nA, a0.z); a0.w = fmaf(vA.w, nA, a0.w);
    }

    float4 bv = *(const float4*)(b + lane * 4);
    float4 o;
    o.x = a0.x + a1.x + a2.x + a3.x + bv.x;
    o.y = a0.y + a1.y + a2.y + a3.y + bv.y;
    o.z = a0.z + a1.z + a2.z + a3.z + bv.z;
    o.w = a0.w + a1.w + a2.w + a3.w + bv.w;
    *(float4*)(out + (size_t)w * C + lane * 4) = o;
}

// ---------------------------------------------------------------------------
extern "C" void kernel_launch(void* const* d_in, const int* in_sizes, int n_in,
                              void* d_out, int out_size) {
    const float* x  = (const float*)d_in[0];
    const void*  ei = d_in[1];
    const float* W  = (const float*)d_in[2];
    const float* b  = (const float*)d_in[3];
    float* out = (float*)d_out;

    int n = in_sizes[0] / C;
    int E = in_sizes[1] / 2;
    int nb = (n + SCAN_B - 1) / SCAN_B;

    detect_dtype<<<1, 256>>>((const int*)ei);
    init_deg<<<(n + 255) / 256, 256>>>(n);
    count_deg<<<(E + 255) / 256, 256>>>(ei, E);
    compute_dinv<<<(n + 255) / 256, 256>>>(n);
    scan_phase1<<<nb, SCAN_B>>>(n);
    scan_phase2<<<1, SCAN_B>>>(nb);
    scan_phase3<<<(n + 255) / 256, 256>>>(n, E);
    fill_csr<<<(E + 255) / 256, 256>>>(ei, E);
    gemm_xw<<<(n + BM - 1) / BM, 256>>>(x, W, n);
    aggregate<<<(n * 32 + 255) / 256, 256>>>(b, out, n);
}

// round 6
// speedup vs baseline: 1.5291x; 1.0050x over previous
#include <cuda_runtime.h>
#include <cuda_bf16.h>
#include <cstdint>

// GCNConv: out = D^-1/2 (A + I) D^-1/2 (x @ W) + b
// Inputs: x[f32 N*128], edge_index[2*E int64 OR int32 -- auto-detected],
//         W[f32 128*128], b[f32 128].  Output: f32 N*128
//
// R6: TF32 mma.sync GEMM (tensor pipe) + CSR gather aggregation.

#define MAX_N 100000
#define MAX_E 1600000
#define C 128
#define SCAN_B 512

__device__ int   g_is64;
__device__ int   g_deg[MAX_N];
__device__ float g_dinv[MAX_N];
__device__ int   g_rowptr[MAX_N + 1];
__device__ int   g_cursor[MAX_N];
__device__ int   g_bsum[(MAX_N + SCAN_B - 1) / SCAN_B + 1];
__device__ int   g_csrc[MAX_E];
__device__ float g_h[(size_t)MAX_N * C];   // 51.2 MB, L2-resident

// ---------------------------------------------------------------------------
// init deg (self loop) + edge dtype detection in one launch.
// int64 payload with values < 2^31 has zero high words at odd int32 slots.
// ---------------------------------------------------------------------------
__global__ void prep(const int* __restrict__ ei32, int n) {
    int i = blockIdx.x * blockDim.x + threadIdx.x;
    if (i < n) g_deg[i] = 1;
    if (blockIdx.x == 0) {
        __shared__ int any_nonzero;
        if (threadIdx.x == 0) any_nonzero = 0;
        __syncthreads();
        for (int k = threadIdx.x; k < 512; k += blockDim.x)
            if (ei32[2 * k + 1] != 0) any_nonzero = 1;
        __syncthreads();
        if (threadIdx.x == 0) g_is64 = (any_nonzero == 0);
    }
}

__device__ __forceinline__ int edge_at(const void* ei, size_t idx, int is64) {
    return is64 ? (int)((const long long*)ei)[idx] : ((const int*)ei)[idx];
}

__global__ void count_deg(const void* __restrict__ ei, int E) {
    int e = blockIdx.x * blockDim.x + threadIdx.x;
    if (e < E) {
        int dst = edge_at(ei, (size_t)E + e, g_is64);
        atomicAdd(&g_deg[dst], 1);
    }
}

// ---------------------------------------------------------------------------
// Exclusive scan of (deg-1) -> rowptr ; also computes dinv (3-phase scan)
// ---------------------------------------------------------------------------
__global__ __launch_bounds__(SCAN_B) void scan_phase1(int n) {
    __shared__ int sh[SCAN_B];
    int i = blockIdx.x * SCAN_B + threadIdx.x;
    int d = (i < n) ? g_deg[i] : 1;
    if (i < n) g_dinv[i] = rsqrtf((float)d);
    int v = (i < n) ? (d - 1) : 0;
    sh[threadIdx.x] = v;
    __syncthreads();
    for (int off = 1; off < SCAN_B; off <<= 1) {
        int t = (threadIdx.x >= off) ? sh[threadIdx.x - off] : 0;
        __syncthreads();
        sh[threadIdx.x] += t;
        __syncthreads();
    }
    if (i < n) g_rowptr[i] = sh[threadIdx.x] - v;   // exclusive
    if (threadIdx.x == SCAN_B - 1) g_bsum[blockIdx.x] = sh[SCAN_B - 1];
}

__global__ __launch_bounds__(SCAN_B) void scan_phase2(int nb) {
    __shared__ int sh[SCAN_B];
    int v = (threadIdx.x < nb) ? g_bsum[threadIdx.x] : 0;
    sh[threadIdx.x] = v;
    __syncthreads();
    for (int off = 1; off < SCAN_B; off <<= 1) {
        int t = (threadIdx.x >= off) ? sh[threadIdx.x - off] : 0;
        __syncthreads();
        sh[threadIdx.x] += t;
        __syncthreads();
    }
    if (threadIdx.x < nb) g_bsum[threadIdx.x] = sh[threadIdx.x] - v;  // exclusive
}

__global__ void scan_phase3(int n, int E) {
    int i = blockIdx.x * blockDim.x + threadIdx.x;
    if (i < n) {
        int r = g_rowptr[i] + g_bsum[i / SCAN_B];
        g_rowptr[i] = r;
        g_cursor[i] = r;
    }
    if (i == 0) g_rowptr[n] = E;
}

__global__ void fill_csr(const void* __restrict__ ei, int E) {
    int e = blockIdx.x * blockDim.x + threadIdx.x;
    if (e >= E) return;
    int is64 = g_is64;
    int src = edge_at(ei, e, is64);
    int dst = edge_at(ei, (size_t)E + e, is64);
    int p = atomicAdd(&g_cursor[dst], 1);
    g_csrc[p] = src;
}

// ---------------------------------------------------------------------------
// TF32 tensor-core GEMM: h[N,128] = x[N,128] @ W[128,128]
// Block tile 64x128, full K=128 in SMEM, 8 warps of 32x32 warp tiles.
// mma.sync.aligned.m16n8k8.row.col.f32.tf32.tf32.f32
// ---------------------------------------------------------------------------
#define GM 64                 // rows per block
#define XSTR 132              // padded smem stride (words)

__device__ __forceinline__ uint32_t f2tf32(float f) {
    uint32_t u;
    asm("cvt.rna.tf32.f32 %0, %1;" : "=r"(u) : "f"(f));
    return u;
}

__global__ __launch_bounds__(256) void gemm_tf32(const float* __restrict__ x,
                                                 const float* __restrict__ W,
                                                 int n) {
    extern __shared__ float smem[];
    float* xs = smem;                 // [GM][XSTR]
    float* ws = smem + GM * XSTR;     // [128][XSTR]

    const int tid  = threadIdx.x;
    const int lane = tid & 31;
    const int wid  = tid >> 5;
    const int wm   = wid >> 2;        // 0..1  (32-row slice)
    const int wn   = wid & 3;         // 0..3  (32-col slice)
    const int g    = lane >> 2;       // 0..7
    const int t    = lane & 3;        // 0..3
    const int row0 = blockIdx.x * GM;

    // Load x tile [GM x 128], convert to tf32(rna). 4 threads/row, 8 float4 each.
    {
        int r = tid >> 2, q = tid & 3;
        int grow = row0 + r;
        const float* xp = x + (size_t)grow * C;
        float* sp = xs + r * XSTR;
#pragma unroll
        for (int i = 0; i < 8; i++) {
            int c4 = (q * 8 + i) * 4;
            float4 v = make_float4(0.f, 0.f, 0.f, 0.f);
            if (grow < n) v = *(const float4*)(xp + c4);
            v.x = __uint_as_float(f2tf32(v.x));
            v.y = __uint_as_float(f2tf32(v.y));
            v.z = __uint_as_float(f2tf32(v.z));
            v.w = __uint_as_float(f2tf32(v.w));
            *(float4*)(sp + c4) = v;
        }
    }
    // Load W [128 x 128], convert. 2 threads/row, 16 float4 each.
    {
        int r = tid >> 1, half = tid & 1;
        const float* wp = W + (size_t)r * C;
        float* sp = ws + r * XSTR;
#pragma unroll
        for (int i = 0; i < 16; i++) {
            int c4 = (half * 16 + i) * 4;
            float4 v = *(const float4*)(wp + c4);
            v.x = __uint_as_float(f2tf32(v.x));
            v.y = __uint_as_float(f2tf32(v.y));
            v.z = __uint_as_float(f2tf32(v.z));
            v.w = __uint_as_float(f2tf32(v.w));
            *(float4*)(sp + c4) = v;
        }
    }
    __syncthreads();

    float acc[2][4][4];
#pragma unroll
    for (int ms = 0; ms < 2; ms++)
#pragma unroll
        for (int ns = 0; ns < 4; ns++)
#pragma unroll
            for (int j = 0; j < 4; j++) acc[ms][ns][j] = 0.f;

#pragma unroll
    for (int k = 0; k < 16; k++) {
        const int kc = k * 8;
        uint32_t a[2][4], bf[4][2];
#pragma unroll
        for (int ms = 0; ms < 2; ms++) {
            const float* base = xs + (wm * 32 + ms * 16) * XSTR + kc;
            a[ms][0] = __float_as_uint(base[g * XSTR + t]);
            a[ms][1] = __float_as_uint(base[(g + 8) * XSTR + t]);
            a[ms][2] = __float_as_uint(base[g * XSTR + t + 4]);
            a[ms][3] = __float_as_uint(base[(g + 8) * XSTR + t + 4]);
        }
#pragma unroll
        for (int ns = 0; ns < 4; ns++) {
            const float* base = ws + kc * XSTR + wn * 32 + ns * 8 + g;
            bf[ns][0] = __float_as_uint(base[t * XSTR]);
            bf[ns][1] = __float_as_uint(base[(t + 4) * XSTR]);
        }
#pragma unroll
        for (int ms = 0; ms < 2; ms++)
#pragma unroll
            for (int ns = 0; ns < 4; ns++) {
                asm volatile(
                    "mma.sync.aligned.m16n8k8.row.col.f32.tf32.tf32.f32 "
                    "{%0,%1,%2,%3}, {%4,%5,%6,%7}, {%8,%9}, {%0,%1,%2,%3};"
                    : "+f"(acc[ms][ns][0]), "+f"(acc[ms][ns][1]),
                      "+f"(acc[ms][ns][2]), "+f"(acc[ms][ns][3])
                    : "r"(a[ms][0]), "r"(a[ms][1]), "r"(a[ms][2]), "r"(a[ms][3]),
                      "r"(bf[ns][0]), "r"(bf[ns][1]));
            }
    }

    // Epilogue: c0/c1 -> row (g), cols t*2, t*2+1 ; c2/c3 -> row (g+8)
#pragma unroll
    for (int ms = 0; ms < 2; ms++) {
        int r = row0 + wm * 32 + ms * 16 + g;
#pragma unroll
        for (int ns = 0; ns < 4; ns++) {
            int c = wn * 32 + ns * 8 + t * 2;
            if (r < n)
                *(float2*)(g_h + (size_t)r * C + c) =
                    make_float2(acc[ms][ns][0], acc[ms][ns][1]);
            if (r + 8 < n)
                *(float2*)(g_h + (size_t)(r + 8) * C + c) =
                    make_float2(acc[ms][ns][2], acc[ms][ns][3]);
        }
    }
}

// ---------------------------------------------------------------------------
// Aggregate: one warp per dst node; register accumulation, fused self-loop
// + bias, single vector store. MLP=4 on h-row gathers.
// ---------------------------------------------------------------------------
__global__ __launch_bounds__(256) void aggregate(const float* __restrict__ b,
                                                 float* __restrict__ out, int n) {
    int w    = (blockIdx.x * blockDim.x + threadIdx.x) >> 5;
    int lane = threadIdx.x & 31;
    if (w >= n) return;

    float di = g_dinv[w];
    int j  = g_rowptr[w];
    int j1 = g_rowptr[w + 1];

    float4 hv = *(const float4*)(g_h + (size_t)w * C + lane * 4);
    float s = di * di;
    float4 a0 = make_float4(hv.x * s, hv.y * s, hv.z * s, hv.w * s);
    float4 a1 = make_float4(0.f, 0.f, 0.f, 0.f);
    float4 a2 = make_float4(0.f, 0.f, 0.f, 0.f);
    float4 a3 = make_float4(0.f, 0.f, 0.f, 0.f);

    for (; j + 3 < j1; j += 4) {
        int sA = g_csrc[j], sB = g_csrc[j + 1], sC = g_csrc[j + 2], sD = g_csrc[j + 3];
        float nA = di * g_dinv[sA];
        float nB = di * g_dinv[sB];
        float nC = di * g_dinv[sC];
        float nD = di * g_dinv[sD];
        float4 vA = *(const float4*)(g_h + (size_t)sA * C + lane * 4);
        float4 vB = *(const float4*)(g_h + (size_t)sB * C + lane * 4);
        float4 vC = *(const float4*)(g_h + (size_t)sC * C + lane * 4);
        float4 vD = *(const float4*)(g_h + (size_t)sD * C + lane * 4);
        a0.x = fmaf(vA.x, nA, a0.x); a0.y = fmaf(vA.y, nA, a0.y);
        a0.z = fmaf(vA.z, nA, a0.z); a0.w = fmaf(vA.w, nA, a0.w);
        a1.x = fmaf(vB.x, nB, a1.x); a1.y = fmaf(vB.y, nB, a1.y);
        a1.z = fmaf(vB.z, nB, a1.z); a1.w = fmaf(vB.w, nB, a1.w);
        a2.x = fmaf(vC.x, nC, a2.x); a2.y = fmaf(vC.y, nC, a2.y);
        a2.z = fmaf(vC.z, nC, a2.z); a2.w = fmaf(vC.w, nC, a2.w);
        a3.x = fmaf(vD.x, nD, a3.x); a3.y = fmaf(vD.y, nD, a3.y);
        a3.z = fmaf(vD.z, nD, a3.z); a3.w = fmaf(vD.w, nD, a3.w);
    }
    for (; j < j1; j++) {
        int sA = g_csrc[j];
        float nA = di * g_dinv[sA];
        float4 vA = *(const float4*)(g_h + (size_t)sA * C + lane * 4);
        a0.x = fmaf(vA.x, nA, a0.x); a0.y = fmaf(vA.y, nA, a0.y);
        a0.z = fmaf(vA.z, nA, a0.z); a0.w = fmaf(vA.w, nA, a0.w);
    }

    float4 bv = *(const float4*)(b + lane * 4);
    float4 o;
    o.x = a0.x + a1.x + a2.x + a3.x + bv.x;
    o.y = a0.y + a1.y + a2.y + a3.y + bv.y;
    o.z = a0.z + a1.z + a2.z + a3.z + bv.z;
    o.w = a0.w + a1.w + a2.w + a3.w + bv.w;
    *(float4*)(out + (size_t)w * C + lane * 4) = o;
}

// ---------------------------------------------------------------------------
extern "C" void kernel_launch(void* const* d_in, const int* in_sizes, int n_in,
                              void* d_out, int out_size) {
    const float* x  = (const float*)d_in[0];
    const void*  ei = d_in[1];
    const float* W  = (const float*)d_in[2];
    const float* b  = (const float*)d_in[3];
    float* out = (float*)d_out;

    int n = in_sizes[0] / C;
    int E = in_sizes[1] / 2;
    int nb = (n + SCAN_B - 1) / SCAN_B;

    const int GEMM_SMEM = (GM * XSTR + 128 * XSTR) * (int)sizeof(float);  // ~101 KB
    cudaFuncSetAttribute(gemm_tf32, cudaFuncAttributeMaxDynamicSharedMemorySize,
                         GEMM_SMEM);

    prep<<<(n + 255) / 256, 256>>>((const int*)ei, n);
    count_deg<<<(E + 255) / 256, 256>>>(ei, E);
    scan_phase1<<<nb, SCAN_B>>>(n);
    scan_phase2<<<1, SCAN_B>>>(nb);
    scan_phase3<<<(n + 255) / 256, 256>>>(n, E);
    fill_csr<<<(E + 255) / 256, 256>>>(ei, E);
    gemm_tf32<<<(n + GM - 1) / GM, 256, GEMM_SMEM>>>(x, W, n);
    aggregate<<<(n * 32 + 255) / 256, 256>>>(b, out, n);
}

// round 7
// speedup vs baseline: 1.6771x; 1.0968x over previous
#include <cuda_runtime.h>
#include <cstdint>

// GCNConv: out = D^-1/2 (A + I) D^-1/2 (x @ W) + b
// R7: 5 kernels (fused dtype-detect, single-pass lookback scan),
//     TF32 mma GEMM with conflict-free frags + dinv-prescale epilogue,
//     CSR gather aggregation with pure-add accumulation.

#define MAX_N 100000
#define MAX_E 1600000
#define C 128
#define SCAN_B 512
#define NB_MAX ((MAX_N + SCAN_B - 1) / SCAN_B)

__device__ int   g_deg[MAX_N];          // edge counts; zeroed at BSS-init and by aggregate tail
__device__ float g_dinv[MAX_N];
__device__ int   g_rowptr[MAX_N + 1];
__device__ int   g_cursor[MAX_N];
__device__ int   g_csrc[MAX_E];
__device__ unsigned long long g_status[NB_MAX];   // lookback: flag<<62 | value
__device__ int   g_ticket;
__device__ float g_h[(size_t)MAX_N * C];          // prescaled h' = (xW)*dinv, L2-resident

// ---------------------------------------------------------------------------
// Per-block edge dtype detection. int64 payload (values < 2^31) has zero high
// words at odd int32 slots; int32 payload has live indices there.
// Requires blockDim.x >= 256.
// ---------------------------------------------------------------------------
__device__ __forceinline__ int detect_is64(const int* __restrict__ ei32) {
    __shared__ int s64;
    if (threadIdx.x == 0) s64 = 1;
    __syncthreads();
    if (threadIdx.x < 256 && ei32[2 * threadIdx.x + 1] != 0) s64 = 0;
    __syncthreads();
    return s64;
}

// ---------------------------------------------------------------------------
// Count in-degree (excl. self loop) + zero scan aux + rowptr[n]=E.
// 4 edges per thread.
// ---------------------------------------------------------------------------
__global__ __launch_bounds__(256) void count_deg(const int* __restrict__ ei32,
                                                 int E, int n, int NB) {
    int is64 = detect_is64(ei32);
    if (blockIdx.x == 0) {
        if (threadIdx.x == 0) { g_ticket = 0; g_rowptr[n] = E; }
        for (int p = threadIdx.x; p < NB; p += 256) g_status[p] = 0ULL;
    }
    int e0 = (blockIdx.x * 256 + threadIdx.x) * 4;
    if (e0 >= E) return;
    int m = E - e0; if (m > 4) m = 4;
    if (is64) {
        const long long* d = (const long long*)ei32 + (size_t)E + e0;
#pragma unroll
        for (int k = 0; k < 4; k++)
            if (k < m) atomicAdd(&g_deg[(int)d[k]], 1);
    } else {
        const int* d = ei32 + (size_t)E + e0;
#pragma unroll
        for (int k = 0; k < 4; k++)
            if (k < m) atomicAdd(&g_deg[d[k]], 1);
    }
}

// ---------------------------------------------------------------------------
// Single-pass exclusive scan of counts -> rowptr/cursor, plus dinv.
// Decoupled lookback, ticket-ordered (no deadlock: partial published before
// any spin; tickets follow block start order). Warp-parallel lookback.
// ---------------------------------------------------------------------------
__global__ __launch_bounds__(SCAN_B) void scan_csr(int n) {
    __shared__ int sh[SCAN_B];
    __shared__ int s_ticket, s_prefix;
    if (threadIdx.x == 0) s_ticket = atomicAdd(&g_ticket, 1);
    __syncthreads();
    const int t = s_ticket;
    const int i = t * SCAN_B + threadIdx.x;

    int cnt = (i < n) ? g_deg[i] : 0;
    if (i < n) g_dinv[i] = rsqrtf((float)(cnt + 1));   // +1 self loop

    sh[threadIdx.x] = cnt;
    __syncthreads();
    for (int off = 1; off < SCAN_B; off <<= 1) {
        int v = (threadIdx.x >= off) ? sh[threadIdx.x - off] : 0;
        __syncthreads();
        sh[threadIdx.x] += v;
        __syncthreads();
    }
    int incl  = sh[threadIdx.x];
    int total = sh[SCAN_B - 1];

    if (threadIdx.x < 32) {
        int lane = threadIdx.x;
        if (lane == 0) {
            if (t == 0) {
                atomicExch(&g_status[0], (2ULL << 62) | (unsigned)total);
                s_prefix = 0;
            } else {
                atomicExch(&g_status[t], (1ULL << 62) | (unsigned)total);
            }
        }
        if (t > 0) {
            long long pref = 0;
            int base = t;
            for (;;) {
                int p = base - 1 - lane;
                int flag = 0, val = 0;
                if (p >= 0) {
                    unsigned long long s;
                    do {
                        s = atomicAdd(&g_status[p], 0ULL);
                        flag = (int)(s >> 62);
                    } while (flag == 0);
                    val = (int)(s & 0xffffffffu);
                }
                unsigned f2 = __ballot_sync(0xffffffffu, p >= 0 && flag == 2);
                int first = f2 ? (__ffs(f2) - 1) : 32;
                int contrib = (p >= 0 && lane <= first) ? val : 0;
#pragma unroll
                for (int off = 16; off; off >>= 1)
                    contrib += __shfl_down_sync(0xffffffffu, contrib, off);
                if (lane == 0) pref += contrib;
                if (f2) break;
                base -= 32;
            }
            if (lane == 0) {
                atomicExch(&g_status[t], (2ULL << 62) | (unsigned)(pref + (long long)total));
                s_prefix = (int)pref;
            }
        }
    }
    __syncthreads();
    if (i < n) {
        int excl = s_prefix + incl - cnt;
        g_rowptr[i] = excl;
        g_cursor[i] = excl;
    }
}

// ---------------------------------------------------------------------------
// Fill CSR: csrc[pos] = src grouped by dst. 4 edges per thread.
// ---------------------------------------------------------------------------
__global__ __launch_bounds__(256) void fill_csr(const int* __restrict__ ei32, int E) {
    int is64 = detect_is64(ei32);
    int e0 = (blockIdx.x * 256 + threadIdx.x) * 4;
    if (e0 >= E) return;
    int m = E - e0; if (m > 4) m = 4;
#pragma unroll
    for (int k = 0; k < 4; k++) {
        if (k >= m) break;
        int e = e0 + k;
        int src, dst;
        if (is64) {
            src = (int)((const long long*)ei32)[e];
            dst = (int)((const long long*)ei32)[(size_t)E + e];
        } else {
            src = ei32[e];
            dst = ei32[(size_t)E + e];
        }
        int p = atomicAdd(&g_cursor[dst], 1);
        g_csrc[p] = src;
    }
}

// ---------------------------------------------------------------------------
// TF32 GEMM: h'[N,128] = (x @ W) * dinv[row]. Block 64x128, full K in SMEM.
// Separate smem strides: SA=132 (A frag bank=4g+t, bijective),
//                        SB=136 (B frag bank=g+8t, bijective) -> conflict-free.
// ---------------------------------------------------------------------------
#define GM 64
#define SA 132
#define SB 136

__device__ __forceinline__ uint32_t f2tf32(float f) {
    uint32_t u;
    asm("cvt.rna.tf32.f32 %0, %1;" : "=r"(u) : "f"(f));
    return u;
}

__global__ __launch_bounds__(256) void gemm_tf32(const float* __restrict__ x,
                                                 const float* __restrict__ W,
                                                 int n) {
    extern __shared__ float smem[];
    float* xs = smem;              // [GM][SA]
    float* ws = smem + GM * SA;    // [128][SB]

    const int tid  = threadIdx.x;
    const int lane = tid & 31;
    const int wid  = tid >> 5;
    const int wm   = wid >> 2;
    const int wn   = wid & 3;
    const int g    = lane >> 2;
    const int t    = lane & 3;
    const int row0 = blockIdx.x * GM;

    {   // x tile [GM x 128] -> tf32
        int r = tid >> 2, q = tid & 3;
        int grow = row0 + r;
        const float* xp = x + (size_t)grow * C;
        float* sp = xs + r * SA;
#pragma unroll
        for (int i = 0; i < 8; i++) {
            int c4 = (q * 8 + i) * 4;
            float4 v = make_float4(0.f, 0.f, 0.f, 0.f);
            if (grow < n) v = *(const float4*)(xp + c4);
            v.x = __uint_as_float(f2tf32(v.x));
            v.y = __uint_as_float(f2tf32(v.y));
            v.z = __uint_as_float(f2tf32(v.z));
            v.w = __uint_as_float(f2tf32(v.w));
            *(float4*)(sp + c4) = v;
        }
    }
    {   // W [128 x 128] -> tf32
        int r = tid >> 1, half = tid & 1;
        const float* wp = W + (size_t)r * C;
        float* sp = ws + r * SB;
#pragma unroll
        for (int i = 0; i < 16; i++) {
            int c4 = (half * 16 + i) * 4;
            float4 v = *(const float4*)(wp + c4);
            v.x = __uint_as_float(f2tf32(v.x));
            v.y = __uint_as_float(f2tf32(v.y));
            v.z = __uint_as_float(f2tf32(v.z));
            v.w = __uint_as_float(f2tf32(v.w));
            *(float4*)(sp + c4) = v;
        }
    }
    __syncthreads();

    float acc[2][4][4];
#pragma unroll
    for (int ms = 0; ms < 2; ms++)
#pragma unroll
        for (int ns = 0; ns < 4; ns++)
#pragma unroll
            for (int j = 0; j < 4; j++) acc[ms][ns][j] = 0.f;

#pragma unroll
    for (int k = 0; k < 16; k++) {
        const int kc = k * 8;
        uint32_t a[2][4], bf[4][2];
#pragma unroll
        for (int ms = 0; ms < 2; ms++) {
            const float* base = xs + (wm * 32 + ms * 16) * SA + kc;
            a[ms][0] = __float_as_uint(base[g * SA + t]);
            a[ms][1] = __float_as_uint(base[(g + 8) * SA + t]);
            a[ms][2] = __float_as_uint(base[g * SA + t + 4]);
            a[ms][3] = __float_as_uint(base[(g + 8) * SA + t + 4]);
        }
#pragma unroll
        for (int ns = 0; ns < 4; ns++) {
            const float* base = ws + kc * SB + wn * 32 + ns * 8 + g;
            bf[ns][0] = __float_as_uint(base[t * SB]);
            bf[ns][1] = __float_as_uint(base[(t + 4) * SB]);
        }
#pragma unroll
        for (int ms = 0; ms < 2; ms++)
#pragma unroll
            for (int ns = 0; ns < 4; ns++) {
                asm volatile(
                    "mma.sync.aligned.m16n8k8.row.col.f32.tf32.tf32.f32 "
                    "{%0,%1,%2,%3}, {%4,%5,%6,%7}, {%8,%9}, {%0,%1,%2,%3};"
                    : "+f"(acc[ms][ns][0]), "+f"(acc[ms][ns][1]),
                      "+f"(acc[ms][ns][2]), "+f"(acc[ms][ns][3])
                    : "r"(a[ms][0]), "r"(a[ms][1]), "r"(a[ms][2]), "r"(a[ms][3]),
                      "r"(bf[ns][0]), "r"(bf[ns][1]));
            }
    }

    // Epilogue: scale by dinv[row] and store h'
#pragma unroll
    for (int ms = 0; ms < 2; ms++) {
        int r = row0 + wm * 32 + ms * 16 + g;
        float s0 = (r < n)     ? g_dinv[r]     : 0.f;
        float s1 = (r + 8 < n) ? g_dinv[r + 8] : 0.f;
#pragma unroll
        for (int ns = 0; ns < 4; ns++) {
            int c = wn * 32 + ns * 8 + t * 2;
            if (r < n)
                *(float2*)(g_h + (size_t)r * C + c) =
                    make_float2(acc[ms][ns][0] * s0, acc[ms][ns][1] * s0);
            if (r + 8 < n)
                *(float2*)(g_h + (size_t)(r + 8) * C + c) =
                    make_float2(acc[ms][ns][2] * s1, acc[ms][ns][3] * s1);
        }
    }
}

// ---------------------------------------------------------------------------
// Aggregate: one warp per dst. out = dinv[w]*(h'[w] + sum h'[src]) + b.
// Pure float4 adds, MLP=4. Tail-resets g_deg for the next run.
// ---------------------------------------------------------------------------
__global__ __launch_bounds__(256) void aggregate(const float* __restrict__ b,
                                                 float* __restrict__ out, int n) {
    int w    = (blockIdx.x * blockDim.x + threadIdx.x) >> 5;
    int lane = threadIdx.x & 31;
    if (w >= n) return;

    float di = g_dinv[w];
    int j  = g_rowptr[w];
    int j1 = g_rowptr[w + 1];
    if (lane == 0) g_deg[w] = 0;      // invariant: counts zeroed for next call

    float4 a0 = *(const float4*)(g_h + (size_t)w * C + lane * 4);  // h'[w]
    float4 a1 = make_float4(0.f, 0.f, 0.f, 0.f);
    float4 a2 = make_float4(0.f, 0.f, 0.f, 0.f);
    float4 a3 = make_float4(0.f, 0.f, 0.f, 0.f);

    for (; j + 3 < j1; j += 4) {
        int sA = g_csrc[j], sB = g_csrc[j + 1], sC = g_csrc[j + 2], sD = g_csrc[j + 3];
        float4 vA = *(const float4*)(g_h + (size_t)sA * C + lane * 4);
        float4 vB = *(const float4*)(g_h + (size_t)sB * C + lane * 4);
        float4 vC = *(const float4*)(g_h + (size_t)sC * C + lane * 4);
        float4 vD = *(const float4*)(g_h + (size_t)sD * C + lane * 4);
        a0.x += vA.x; a0.y += vA.y; a0.z += vA.z; a0.w += vA.w;
        a1.x += vB.x; a1.y += vB.y; a1.z += vB.z; a1.w += vB.w;
        a2.x += vC.x; a2.y += vC.y; a2.z += vC.z; a2.w += vC.w;
        a3.x += vD.x; a3.y += vD.y; a3.z += vD.z; a3.w += vD.w;
    }
    for (; j < j1; j++) {
        int sA = g_csrc[j];
        float4 vA = *(const float4*)(g_h + (size_t)sA * C + lane * 4);
        a0.x += vA.x; a0.y += vA.y; a0.z += vA.z; a0.w += vA.w;
    }

    float4 bv = *(const float4*)(b + lane * 4);
    float4 o;
    o.x = fmaf(di, a0.x + a1.x + a2.x + a3.x, bv.x);
    o.y = fmaf(di, a0.y + a1.y + a2.y + a3.y, bv.y);
    o.z = fmaf(di, a0.z + a1.z + a2.z + a3.z, bv.z);
    o.w = fmaf(di, a0.w + a1.w + a2.w + a3.w, bv.w);
    *(float4*)(out + (size_t)w * C + lane * 4) = o;
}

// ---------------------------------------------------------------------------
extern "C" void kernel_launch(void* const* d_in, const int* in_sizes, int n_in,
                              void* d_out, int out_size) {
    const float* x  = (const float*)d_in[0];
    const int*   ei = (const int*)d_in[1];
    const float* W  = (const float*)d_in[2];
    const float* b  = (const float*)d_in[3];
    float* out = (float*)d_out;

    int n  = in_sizes[0] / C;
    int E  = in_sizes[1] / 2;
    int NB = (n + SCAN_B - 1) / SCAN_B;
    int EB = (E + 1023) / 1024;

    const int GEMM_SMEM = (GM * SA + 128 * SB) * (int)sizeof(float);  // 103424 B
    cudaFuncSetAttribute(gemm_tf32, cudaFuncAttributeMaxDynamicSharedMemorySize,
                         GEMM_SMEM);

    count_deg<<<EB, 256>>>(ei, E, n, NB);
    scan_csr<<<NB, SCAN_B>>>(n);
    fill_csr<<<EB, 256>>>(ei, E);
    gemm_tf32<<<(n + GM - 1) / GM, 256, GEMM_SMEM>>>(x, W, n);
    aggregate<<<(n * 32 + 255) / 256, 256>>>(b, out, n);
}

// round 8
// speedup vs baseline: 1.9436x; 1.1589x over previous
#include <cuda_runtime.h>
#include <cstdint>

// GCNConv: out = D^-1/2 (A + I) D^-1/2 (x @ W) + b
// R8: persistent-W TF32 GEMM (pre-permuted tf32 B in global, LDS.64 B frags,
//     register-prefetched x tiles) + single-pass lookback CSR + gather agg.

#define MAX_N 100000
#define MAX_E 1600000
#define C 128
#define SCAN_B 512
#define NB_MAX ((MAX_N + SCAN_B - 1) / SCAN_B)

#define GM 64          // rows per tile
#define SA 132         // x smem row stride (words) -- A frags conflict-free
#define SBW 264        // wf pair-row stride (words), 264 % 32 == 8 -> conflict-free
#define GEMM_GRID_MAX 296

__device__ int   g_deg[MAX_N];
__device__ float g_dinv[MAX_N];
__device__ int   g_rowptr[MAX_N + 1];
__device__ int   g_cursor[MAX_N];
__device__ int   g_csrc[MAX_E];
__device__ unsigned long long g_status[NB_MAX];
__device__ int   g_ticket;
__device__ float g_wf[64 * SBW];                  // tf32 W, pair-permuted rows
__device__ float g_h[(size_t)MAX_N * C];          // h' = (xW)*dinv, L2-resident

__device__ __forceinline__ uint32_t f2tf32(float f) {
    uint32_t u;
    asm("cvt.rna.tf32.f32 %0, %1;" : "=r"(u) : "f"(f));
    return u;
}
__device__ __forceinline__ float tf32f(float f) { return __uint_as_float(f2tf32(f)); }

// ---------------------------------------------------------------------------
// Per-block edge dtype detection (int64 payload w/ values < 2^31 has zero high
// words at odd int32 slots). Requires blockDim.x >= 256.
// ---------------------------------------------------------------------------
__device__ __forceinline__ int detect_is64(const int* __restrict__ ei32) {
    __shared__ int s64;
    if (threadIdx.x == 0) s64 = 1;
    __syncthreads();
    if (threadIdx.x < 256 && ei32[2 * threadIdx.x + 1] != 0) s64 = 0;
    __syncthreads();
    return s64;
}

// ---------------------------------------------------------------------------
// count_deg: in-degree (excl self loop), zero scan aux, rowptr[n]=E,
// and (block wblk) build g_wf = tf32(W) in pair-permuted layout.
// ---------------------------------------------------------------------------
__global__ __launch_bounds__(256) void count_deg(const int* __restrict__ ei32,
                                                 const float* __restrict__ W,
                                                 int E, int n, int NB) {
    int is64 = detect_is64(ei32);
    if (blockIdx.x == 0) {
        if (threadIdx.x == 0) { g_ticket = 0; g_rowptr[n] = E; }
        for (int p = threadIdx.x; p < NB; p += 256) g_status[p] = 0ULL;
    }
    int wblk = (gridDim.x > 1) ? 1 : 0;
    if (blockIdx.x == wblk) {
        for (int idx = threadIdx.x; idx < 64 * 128; idx += 256) {
            int p = idx >> 7, c = idx & 127;
            int k8 = p >> 2, t = p & 3;
            g_wf[p * SBW + 2 * c]     = tf32f(W[(size_t)(k8 * 8 + t) * C + c]);
            g_wf[p * SBW + 2 * c + 1] = tf32f(W[(size_t)(k8 * 8 + t + 4) * C + c]);
        }
    }
    int e0 = (blockIdx.x * 256 + threadIdx.x) * 4;
    if (e0 >= E) return;
    int m = E - e0; if (m > 4) m = 4;
    if (is64) {
        const long long* d = (const long long*)ei32 + (size_t)E + e0;
#pragma unroll
        for (int k = 0; k < 4; k++)
            if (k < m) atomicAdd(&g_deg[(int)d[k]], 1);
    } else {
        const int* d = ei32 + (size_t)E + e0;
#pragma unroll
        for (int k = 0; k < 4; k++)
            if (k < m) atomicAdd(&g_deg[d[k]], 1);
    }
}

// ---------------------------------------------------------------------------
// Single-pass exclusive scan (decoupled lookback, ticket-ordered) + dinv.
// ---------------------------------------------------------------------------
__global__ __launch_bounds__(SCAN_B) void scan_csr(int n) {
    __shared__ int sh[SCAN_B];
    __shared__ int s_ticket, s_prefix;
    if (threadIdx.x == 0) s_ticket = atomicAdd(&g_ticket, 1);
    __syncthreads();
    const int t = s_ticket;
    const int i = t * SCAN_B + threadIdx.x;

    int cnt = (i < n) ? g_deg[i] : 0;
    if (i < n) g_dinv[i] = rsqrtf((float)(cnt + 1));

    sh[threadIdx.x] = cnt;
    __syncthreads();
    for (int off = 1; off < SCAN_B; off <<= 1) {
        int v = (threadIdx.x >= off) ? sh[threadIdx.x - off] : 0;
        __syncthreads();
        sh[threadIdx.x] += v;
        __syncthreads();
    }
    int incl  = sh[threadIdx.x];
    int total = sh[SCAN_B - 1];

    if (threadIdx.x < 32) {
        int lane = threadIdx.x;
        if (lane == 0) {
            if (t == 0) {
                atomicExch(&g_status[0], (2ULL << 62) | (unsigned)total);
                s_prefix = 0;
            } else {
                atomicExch(&g_status[t], (1ULL << 62) | (unsigned)total);
            }
        }
        if (t > 0) {
            long long pref = 0;
            int base = t;
            for (;;) {
                int p = base - 1 - lane;
                int flag = 0, val = 0;
                if (p >= 0) {
                    unsigned long long s;
                    do {
                        s = atomicAdd(&g_status[p], 0ULL);
                        flag = (int)(s >> 62);
                    } while (flag == 0);
                    val = (int)(s & 0xffffffffu);
                }
                unsigned f2 = __ballot_sync(0xffffffffu, p >= 0 && flag == 2);
                int first = f2 ? (__ffs(f2) - 1) : 32;
                int contrib = (p >= 0 && lane <= first) ? val : 0;
#pragma unroll
                for (int off = 16; off; off >>= 1)
                    contrib += __shfl_down_sync(0xffffffffu, contrib, off);
                if (lane == 0) pref += contrib;
                if (f2) break;
                base -= 32;
            }
            if (lane == 0) {
                atomicExch(&g_status[t], (2ULL << 62) | (unsigned)(pref + (long long)total));
                s_prefix = (int)pref;
            }
        }
    }
    __syncthreads();
    if (i < n) {
        int excl = s_prefix + incl - cnt;
        g_rowptr[i] = excl;
        g_cursor[i] = excl;
    }
}

// ---------------------------------------------------------------------------
// Fill CSR: csrc[pos] = src grouped by dst. 4 edges per thread.
// ---------------------------------------------------------------------------
__global__ __launch_bounds__(256) void fill_csr(const int* __restrict__ ei32, int E) {
    int is64 = detect_is64(ei32);
    int e0 = (blockIdx.x * 256 + threadIdx.x) * 4;
    if (e0 >= E) return;
    int m = E - e0; if (m > 4) m = 4;
#pragma unroll
    for (int k = 0; k < 4; k++) {
        if (k >= m) break;
        int e = e0 + k;
        int src, dst;
        if (is64) {
            src = (int)((const long long*)ei32)[e];
            dst = (int)((const long long*)ei32)[(size_t)E + e];
        } else {
            src = ei32[e];
            dst = ei32[(size_t)E + e];
        }
        int p = atomicAdd(&g_cursor[dst], 1);
        g_csrc[p] = src;
    }
}

// ---------------------------------------------------------------------------
// Persistent TF32 GEMM: h'[r] = (x@W)[r] * dinv[r].
// Each block: load pre-permuted W->smem once, then loop row-tiles with
// register-prefetched x. Mainloop: 8 LDS.32 (A) + 4 LDS.64 (B) + 8 MMA /kstep.
// ---------------------------------------------------------------------------
__global__ __launch_bounds__(256, 2) void gemm_tf32(const float* __restrict__ x,
                                                    int n, int ntiles) {
    extern __shared__ float smem[];
    float* xs = smem;              // [GM][SA]
    float* ws = smem + GM * SA;    // [64][SBW] pair-rows

    const int tid  = threadIdx.x;
    const int lane = tid & 31;
    const int wid  = tid >> 5;
    const int wm   = wid >> 2;
    const int wn   = wid & 3;
    const int g    = lane >> 2;
    const int t    = lane & 3;
    const int lr   = tid >> 2;     // load row 0..63
    const int lq   = tid & 3;      // load quarter

    // Copy pre-permuted tf32 W into smem (once per block)
    {
        const float4* wsrc = (const float4*)g_wf;
        float4* wdst = (float4*)ws;
        for (int i = tid; i < 64 * SBW / 4; i += 256) wdst[i] = wsrc[i];
    }

    // Prefetch first tile into registers
    float4 xr[8];
    int tile = blockIdx.x;
    if (tile < ntiles) {
        int grow = tile * GM + lr;
        const float* xp = x + (size_t)grow * C;
#pragma unroll
        for (int i = 0; i < 8; i++)
            xr[i] = (grow < n) ? *(const float4*)(xp + (lq * 8 + i) * 4)
                               : make_float4(0.f, 0.f, 0.f, 0.f);
    }

    for (; tile < ntiles; tile += gridDim.x) {
        __syncthreads();                        // xs free (prev compute done)
        {   // cvt + store this tile's x
            float* sp = xs + lr * SA;
#pragma unroll
            for (int i = 0; i < 8; i++) {
                float4 v = xr[i];
                v.x = tf32f(v.x); v.y = tf32f(v.y);
                v.z = tf32f(v.z); v.w = tf32f(v.w);
                *(float4*)(sp + (lq * 8 + i) * 4) = v;
            }
        }
        __syncthreads();

        // Prefetch next tile (LDG latency hidden behind compute below)
        int next = tile + gridDim.x;
        if (next < ntiles) {
            int grow = next * GM + lr;
            const float* xp = x + (size_t)grow * C;
#pragma unroll
            for (int i = 0; i < 8; i++)
                xr[i] = (grow < n) ? *(const float4*)(xp + (lq * 8 + i) * 4)
                                   : make_float4(0.f, 0.f, 0.f, 0.f);
        }

        float acc[2][4][4];
#pragma unroll
        for (int ms = 0; ms < 2; ms++)
#pragma unroll
            for (int ns = 0; ns < 4; ns++)
#pragma unroll
                for (int j = 0; j < 4; j++) acc[ms][ns][j] = 0.f;

#pragma unroll
        for (int k = 0; k < 16; k++) {
            uint32_t a[2][4];
#pragma unroll
            for (int ms = 0; ms < 2; ms++) {
                const float* base = xs + (wm * 32 + ms * 16) * SA + k * 8;
                a[ms][0] = __float_as_uint(base[g * SA + t]);
                a[ms][1] = __float_as_uint(base[(g + 8) * SA + t]);
                a[ms][2] = __float_as_uint(base[g * SA + t + 4]);
                a[ms][3] = __float_as_uint(base[(g + 8) * SA + t + 4]);
            }
#pragma unroll
            for (int ns = 0; ns < 4; ns++) {
                float2 bv = *(const float2*)(ws + (k * 4 + t) * SBW
                                             + 2 * (wn * 32 + ns * 8 + g));
                uint32_t b0 = __float_as_uint(bv.x);
                uint32_t b1 = __float_as_uint(bv.y);
#pragma unroll
                for (int ms = 0; ms < 2; ms++) {
                    asm volatile(
                        "mma.sync.aligned.m16n8k8.row.col.f32.tf32.tf32.f32 "
                        "{%0,%1,%2,%3}, {%4,%5,%6,%7}, {%8,%9}, {%0,%1,%2,%3};"
                        : "+f"(acc[ms][ns][0]), "+f"(acc[ms][ns][1]),
                          "+f"(acc[ms][ns][2]), "+f"(acc[ms][ns][3])
                        : "r"(a[ms][0]), "r"(a[ms][1]), "r"(a[ms][2]), "r"(a[ms][3]),
                          "r"(b0), "r"(b1));
                }
            }
        }

        // Epilogue: scale by dinv[row], store h'
        int row0 = tile * GM;
#pragma unroll
        for (int ms = 0; ms < 2; ms++) {
            int r = row0 + wm * 32 + ms * 16 + g;
            float s0 = (r < n)     ? g_dinv[r]     : 0.f;
            float s1 = (r + 8 < n) ? g_dinv[r + 8] : 0.f;
#pragma unroll
            for (int ns = 0; ns < 4; ns++) {
                int c = wn * 32 + ns * 8 + t * 2;
                if (r < n)
                    *(float2*)(g_h + (size_t)r * C + c) =
                        make_float2(acc[ms][ns][0] * s0, acc[ms][ns][1] * s0);
                if (r + 8 < n)
                    *(float2*)(g_h + (size_t)(r + 8) * C + c) =
                        make_float2(acc[ms][ns][2] * s1, acc[ms][ns][3] * s1);
            }
        }
    }
}

// ---------------------------------------------------------------------------
// Aggregate: one warp per dst. out = dinv[w]*(h'[w] + sum h'[src]) + b.
// ---------------------------------------------------------------------------
__global__ __launch_bounds__(256) void aggregate(const float* __restrict__ b,
                                                 float* __restrict__ out, int n) {
    int w    = (blockIdx.x * blockDim.x + threadIdx.x) >> 5;
    int lane = threadIdx.x & 31;
    if (w >= n) return;

    float di = g_dinv[w];
    int j  = g_rowptr[w];
    int j1 = g_rowptr[w + 1];
    if (lane == 0) g_deg[w] = 0;      // reset counts for next call

    float4 a0 = *(const float4*)(g_h + (size_t)w * C + lane * 4);
    float4 a1 = make_float4(0.f, 0.f, 0.f, 0.f);
    float4 a2 = make_float4(0.f, 0.f, 0.f, 0.f);
    float4 a3 = make_float4(0.f, 0.f, 0.f, 0.f);

    for (; j + 3 < j1; j += 4) {
        int sA = g_csrc[j], sB = g_csrc[j + 1], sC = g_csrc[j + 2], sD = g_csrc[j + 3];
        float4 vA = *(const float4*)(g_h + (size_t)sA * C + lane * 4);
        float4 vB = *(const float4*)(g_h + (size_t)sB * C + lane * 4);
        float4 vC = *(const float4*)(g_h + (size_t)sC * C + lane * 4);
        float4 vD = *(const float4*)(g_h + (size_t)sD * C + lane * 4);
        a0.x += vA.x; a0.y += vA.y; a0.z += vA.z; a0.w += vA.w;
        a1.x += vB.x; a1.y += vB.y; a1.z += vB.z; a1.w += vB.w;
        a2.x += vC.x; a2.y += vC.y; a2.z += vC.z; a2.w += vC.w;
        a3.x += vD.x; a3.y += vD.y; a3.z += vD.z; a3.w += vD.w;
    }
    for (; j < j1; j++) {
        int sA = g_csrc[j];
        float4 vA = *(const float4*)(g_h + (size_t)sA * C + lane * 4);
        a0.x += vA.x; a0.y += vA.y; a0.z += vA.z; a0.w += vA.w;
    }

    float4 bv = *(const float4*)(b + lane * 4);
    float4 o;
    o.x = fmaf(di, a0.x + a1.x + a2.x + a3.x, bv.x);
    o.y = fmaf(di, a0.y + a1.y + a2.y + a3.y, bv.y);
    o.z = fmaf(di, a0.z + a1.z + a2.z + a3.z, bv.z);
    o.w = fmaf(di, a0.w + a1.w + a2.w + a3.w, bv.w);
    *(float4*)(out + (size_t)w * C + lane * 4) = o;
}

// ---------------------------------------------------------------------------
extern "C" void kernel_launch(void* const* d_in, const int* in_sizes, int n_in,
                              void* d_out, int out_size) {
    const float* x  = (const float*)d_in[0];
    const int*   ei = (const int*)d_in[1];
    const float* W  = (const float*)d_in[2];
    const float* b  = (const float*)d_in[3];
    float* out = (float*)d_out;

    int n  = in_sizes[0] / C;
    int E  = in_sizes[1] / 2;
    int NB = (n + SCAN_B - 1) / SCAN_B;
    int EB = (E + 1023) / 1024;
    int ntiles = (n + GM - 1) / GM;
    int ggrid = ntiles < GEMM_GRID_MAX ? ntiles : GEMM_GRID_MAX;

    const int GEMM_SMEM = (GM * SA + 64 * SBW) * (int)sizeof(float);  // 101376 B
    cudaFuncSetAttribute(gemm_tf32, cudaFuncAttributeMaxDynamicSharedMemorySize,
                         GEMM_SMEM);

    count_deg<<<EB, 256>>>(ei, W, E, n, NB);
    scan_csr<<<NB, SCAN_B>>>(n);
    fill_csr<<<EB, 256>>>(ei, E);
    gemm_tf32<<<ggrid, 256, GEMM_SMEM>>>(x, n, ntiles);
    aggregate<<<(n * 32 + 255) / 256, 256>>>(b, out, n);
}